// round 4
// baseline (speedup 1.0000x reference)
#include <cuda_runtime.h>
#include <cstdint>

// CrossAttMultiplexer collapses analytically:
//   out[n,i] = v[n,i] * sum_j softmax(...)[n,i,j] = s[n,i] * WV[0]
// Pure HBM stream: read s (6.29MB), write out (6.29MB).
//
// R4: warp-issued LDG is scoreboard-latency-bound at this size (R1-R3 all
// ~5.5-6.2us kernel, DRAM<15%). Switch the data movement to cp.async.bulk
// (1D TMA): the DMA queue keeps bytes in flight independent of warp count.
// 384 CTAs x 16KB chunks: bulk-load -> smem multiply -> bulk-store.

#define CHUNK_BYTES  16384
#define CHUNK_FLOAT4 1024        // 16KB / 16B
#define THREADS      256
#define F4_PER_THR   4           // 1024 / 256

__global__ void __launch_bounds__(THREADS)
scale_bulk_kernel(const float* __restrict__ s,
                  const float* __restrict__ WV,
                  float* __restrict__ out) {
    __shared__ alignas(128) float4 buf[CHUNK_FLOAT4];
    __shared__ alignas(8) uint64_t mbar;

    const int tid = threadIdx.x;
    const float wv = __ldg(WV);
    const size_t off = (size_t)blockIdx.x * CHUNK_BYTES;

    const uint32_t mbar_a = (uint32_t)__cvta_generic_to_shared(&mbar);
    const uint32_t buf_a  = (uint32_t)__cvta_generic_to_shared(buf);

    if (tid == 0) {
        asm volatile("mbarrier.init.shared.b64 [%0], 1;" :: "r"(mbar_a));
    }
    __syncthreads();

    if (tid == 0) {
        asm volatile("mbarrier.arrive.expect_tx.shared.b64 _, [%0], %1;"
                     :: "r"(mbar_a), "r"((uint32_t)CHUNK_BYTES) : "memory");
        asm volatile(
            "cp.async.bulk.shared::cta.global.mbarrier::complete_tx::bytes "
            "[%0], [%1], %2, [%3];"
            :: "r"(buf_a), "l"((const char*)s + off),
               "r"((uint32_t)CHUNK_BYTES), "r"(mbar_a) : "memory");
    }

    // Wait for bulk load completion (phase 0).
    {
        uint32_t done;
        asm volatile(
            "{\n\t.reg .pred p;\n\t"
            "mbarrier.try_wait.parity.shared::cta.b64 p, [%1], 0;\n\t"
            "selp.b32 %0, 1, 0, p;\n\t}"
            : "=r"(done) : "r"(mbar_a) : "memory");
        while (!done) {
            asm volatile(
                "{\n\t.reg .pred p;\n\t"
                "mbarrier.try_wait.parity.shared::cta.b64 p, [%1], 0, 0x989680;\n\t"
                "selp.b32 %0, 1, 0, p;\n\t}"
                : "=r"(done) : "r"(mbar_a) : "memory");
        }
    }

    // Multiply in shared memory (conflict-free: stride-256 float4s).
#pragma unroll
    for (int i = 0; i < F4_PER_THR; i++) {
        float4 v = buf[tid + i * THREADS];
        v.x *= wv; v.y *= wv; v.z *= wv; v.w *= wv;
        buf[tid + i * THREADS] = v;
    }
    __syncthreads();

    if (tid == 0) {
        asm volatile("fence.proxy.async.shared::cta;" ::: "memory");
        asm volatile(
            "cp.async.bulk.global.shared::cta.bulk_group [%0], [%1], %2;"
            :: "l"((char*)out + off), "r"(buf_a),
               "r"((uint32_t)CHUNK_BYTES) : "memory");
        asm volatile("cp.async.bulk.commit_group;" ::: "memory");
        // Drain before CTA exit (smem is deallocated on exit).
        asm volatile("cp.async.bulk.wait_group 0;" ::: "memory");
    }
    __syncthreads();
}

// Generic fallback (bounds-checked, grid-stride) for sizes that don't tile.
__global__ void scale_generic_kernel(const float* __restrict__ s,
                                     const float* __restrict__ WV,
                                     float* __restrict__ out, int n) {
    const float wv = WV[0];
    for (int i = blockIdx.x * blockDim.x + threadIdx.x; i < n;
         i += gridDim.x * blockDim.x)
        out[i] = s[i] * wv;
}

extern "C" void kernel_launch(void* const* d_in, const int* in_sizes, int n_in,
                              void* d_out, int out_size) {
    // metadata order: x, s, WQ, WK, WV
    const float* s  = (const float*)d_in[1];
    const float* WV = (const float*)d_in[4];
    float* out = (float*)d_out;

    long long bytes = (long long)out_size * 4;   // fp32 out, same count as s
    if (bytes % CHUNK_BYTES == 0) {
        int blocks = (int)(bytes / CHUNK_BYTES);   // 384 for the bench shape
        scale_bulk_kernel<<<blocks, THREADS>>>(s, WV, out);
    } else {
        int blocks = (out_size + 255) / 256;
        if (blocks > 1184) blocks = 1184;
        scale_generic_kernel<<<blocks, 256>>>(s, WV, out, out_size);
    }
}

// round 5
// speedup vs baseline: 1.0386x; 1.0386x over previous
#include <cuda_runtime.h>

// CrossAttMultiplexer collapses analytically:
//   out[n,i] = v[n,i] * sum_j softmax(...)[n,i,j] = s[n,i] * WV[0]
// Pure HBM stream: read s (6.29MB), write out (6.29MB).
//
// R5: four distinct engines (LDG occ/MLP variants, bulk-DMA) all hit
// kernel ~5.5-6.2us, e2e ~6.85-6.88 -> duration is dominated by a fixed
// dispatch/ramp term, streaming is ~2us. This round minimizes the dispatch
// term: exactly one wave (592 CTAs = 4/SM), persistent batched grid-stride,
// and zero-reuse streaming cache hints (__ldcs/__stcs, evict-first).

#define THREADS 256
#define BATCH   4

__global__ void __launch_bounds__(THREADS)
scale_stream_kernel(const float4* __restrict__ s4,
                    const float* __restrict__ WV,
                    float4* __restrict__ out4,
                    int n4) {
    const float wv = __ldg(WV);
    const int stride = gridDim.x * THREADS;
    int idx = blockIdx.x * THREADS + threadIdx.x;

    for (int base = idx; base < n4; base += BATCH * stride) {
        float4 v[BATCH];
        int   id[BATCH];
        bool   p[BATCH];
#pragma unroll
        for (int u = 0; u < BATCH; u++) {
            id[u] = base + u * stride;
            p[u]  = id[u] < n4;
            if (p[u]) v[u] = __ldcs(&s4[id[u]]);   // front-batched, evict-first
        }
#pragma unroll
        for (int u = 0; u < BATCH; u++) {
            if (p[u]) {
                v[u].x *= wv; v[u].y *= wv; v[u].z *= wv; v[u].w *= wv;
                __stcs(&out4[id[u]], v[u]);        // streaming store
            }
        }
    }
}

// Scalar fallback for n not divisible by 4.
__global__ void scale_generic_kernel(const float* __restrict__ s,
                                     const float* __restrict__ WV,
                                     float* __restrict__ out, int n) {
    const float wv = WV[0];
    for (int i = blockIdx.x * blockDim.x + threadIdx.x; i < n;
         i += gridDim.x * blockDim.x)
        out[i] = __ldcs(&s[i]) * wv;
}

extern "C" void kernel_launch(void* const* d_in, const int* in_sizes, int n_in,
                              void* d_out, int out_size) {
    // metadata order: x, s, WQ, WK, WV
    const float* s  = (const float*)d_in[1];
    const float* WV = (const float*)d_in[4];
    float* out = (float*)d_out;

    int n = out_size;
    if ((n & 3) == 0) {
        int n4 = n >> 2;                       // 393,216
        int blocks = 592;                      // 4 CTAs/SM * 148 SMs, one wave
        int needed = (n4 + THREADS - 1) / THREADS;
        if (blocks > needed) blocks = needed;  // tiny-input safety
        scale_stream_kernel<<<blocks, THREADS>>>((const float4*)s, WV,
                                                 (float4*)out, n4);
    } else {
        int blocks = (n + 255) / 256;
        if (blocks > 1184) blocks = 1184;
        scale_generic_kernel<<<blocks, 256>>>(s, WV, out, n);
    }
}